// round 7
// baseline (speedup 1.0000x reference)
#include <cuda_runtime.h>

// exp(Q*t) for 2,097,152 independent 4x4 fp32 matrices.
// Packed f32x2 + Paterson-Stockmeyer degree-8 Taylor (theta=1) + squaring.
// R7: PERSISTENT grid (444 blocks = 3/SM, one wave) + grid-stride loop with
// register double-buffer prefetch: next matrix's loads issue before current
// matrix's compute, hiding DRAM latency in-thread instead of via scarce TLP,
// and eliminating ~13 block-wave transitions of the non-persistent launch.

#define SEQ_SHIFT 15
#define NMAT (64 * 32768)
#define TPB 256
#define NBLOCKS (148 * 3)            // 444: exactly 3 CTAs per SM
#define STRIDE (TPB * NBLOCKS)       // 113664 threads

typedef unsigned long long u64;

__device__ __forceinline__ u64 pack2(float lo, float hi) {
    u64 r; asm("mov.b64 %0, {%1, %2};" : "=l"(r) : "f"(lo), "f"(hi)); return r;
}
__device__ __forceinline__ void unpack2(u64 v, float& lo, float& hi) {
    asm("mov.b64 {%0, %1}, %2;" : "=f"(lo), "=f"(hi) : "l"(v));
}
__device__ __forceinline__ u64 fma2(u64 a, u64 b, u64 c) {
    u64 d; asm("fma.rn.f32x2 %0, %1, %2, %3;" : "=l"(d) : "l"(a), "l"(b), "l"(c)); return d;
}
__device__ __forceinline__ u64 mul2(u64 a, u64 b) {
    u64 d; asm("mul.rn.f32x2 %0, %1, %2;" : "=l"(d) : "l"(a), "l"(b)); return d;
}
__device__ __forceinline__ u64 add2(u64 a, u64 b) {
    u64 d; asm("add.rn.f32x2 %0, %1, %2;" : "=l"(d) : "l"(a), "l"(b)); return d;
}
__device__ __forceinline__ u64 abs2(u64 v) { return v & 0x7FFFFFFF7FFFFFFFull; }

// C = A*B. Ab = 16 broadcast-packed scalars; B, C = 8 packed row-pairs.
__device__ __forceinline__ void mm4p(const u64* __restrict__ Ab,
                                     const u64* __restrict__ B,
                                     u64* __restrict__ C) {
#pragma unroll
    for (int i = 0; i < 4; ++i) {
#pragma unroll
        for (int jp = 0; jp < 2; ++jp) {
            u64 acc = mul2(Ab[i * 4 + 0], B[0 * 2 + jp]);
            acc = fma2(Ab[i * 4 + 1], B[1 * 2 + jp], acc);
            acc = fma2(Ab[i * 4 + 2], B[2 * 2 + jp], acc);
            acc = fma2(Ab[i * 4 + 3], B[3 * 2 + jp], acc);
            C[i * 2 + jp] = acc;
        }
    }
}

__device__ __forceinline__ void mm4p_acc(const u64* __restrict__ Ab,
                                         const u64* __restrict__ B,
                                         const u64* __restrict__ D,
                                         u64* __restrict__ C) {
#pragma unroll
    for (int i = 0; i < 4; ++i) {
#pragma unroll
        for (int jp = 0; jp < 2; ++jp) {
            u64 acc = fma2(Ab[i * 4 + 0], B[0 * 2 + jp], D[i * 2 + jp]);
            acc = fma2(Ab[i * 4 + 1], B[1 * 2 + jp], acc);
            acc = fma2(Ab[i * 4 + 2], B[2 * 2 + jp], acc);
            acc = fma2(Ab[i * 4 + 3], B[3 * 2 + jp], acc);
            C[i * 2 + jp] = acc;
        }
    }
}

__device__ __forceinline__ void bcast(const u64* __restrict__ Rp,
                                      u64* __restrict__ Rb) {
#pragma unroll
    for (int i = 0; i < 8; ++i) {
        float lo, hi;
        unpack2(Rp[i], lo, hi);
        Rb[2 * i]     = pack2(lo, lo);
        Rb[2 * i + 1] = pack2(hi, hi);
    }
}

// expm of one matrix (packed row-pairs in Ap), result stored to out+idx.
__device__ __forceinline__ void expm_one(const u64* __restrict__ Ap, float t,
                                         float* __restrict__ out, int idx) {
    // inf-norm(A) * t
    u64 q0 = add2(abs2(Ap[0]), abs2(Ap[1]));
    u64 q1 = add2(abs2(Ap[2]), abs2(Ap[3]));
    u64 q2 = add2(abs2(Ap[4]), abs2(Ap[5]));
    u64 q3 = add2(abs2(Ap[6]), abs2(Ap[7]));
    float a0, b0, a1, b1, a2, b2, a3, b3;
    unpack2(q0, a0, b0); unpack2(q1, a1, b1);
    unpack2(q2, a2, b2); unpack2(q3, a3, b3);
    const float nrm = fmaxf(fmaxf(a0 + b0, a1 + b1), fmaxf(a2 + b2, a3 + b3)) * t;

    // s ~ ceil(log2(nrm)) via exponent extraction; clamp [0,16]; warp-max.
    int s = (int)(__float_as_uint(nrm) >> 23) - 126;
    s = max(0, min(16, s));
    const unsigned sw = __reduce_max_sync(0xFFFFFFFFu, (unsigned)s);

    const float scale = t * __uint_as_float((127u - sw) << 23);
    const u64 sc2 = pack2(scale, scale);

    u64 Xp[8];
#pragma unroll
    for (int i = 0; i < 8; ++i) Xp[i] = mul2(Ap[i], sc2);

    u64 Xb[16];
    bcast(Xp, Xb);

    u64 X2[8], X3[8];
    mm4p(Xb, Xp, X2);
    mm4p(Xb, X2, X3);

    u64 X3b[16];
    bcast(X3, X3b);

    const float c2 = 1.0f / 2.0f;
    const float c3 = 1.0f / 6.0f,   c4 = 1.0f / 24.0f,   c5 = 1.0f / 120.0f;
    const float c6 = 1.0f / 720.0f, c7 = 1.0f / 5040.0f, c8 = 1.0f / 40320.0f;

    u64 B0[8], B1[8], B2[8];
#pragma unroll
    for (int i = 0; i < 4; ++i) {
#pragma unroll
        for (int jp = 0; jp < 2; ++jp) {
            const int p = i * 2 + jp;
            const bool dlo = (jp == (i >> 1)) && ((i & 1) == 0);
            const bool dhi = (jp == (i >> 1)) && ((i & 1) == 1);
            const u64 i1  = pack2(dlo ? 1.0f : 0.0f, dhi ? 1.0f : 0.0f);
            const u64 ic3 = pack2(dlo ? c3 : 0.0f,   dhi ? c3 : 0.0f);
            const u64 ic6 = pack2(dlo ? c6 : 0.0f,   dhi ? c6 : 0.0f);
            B0[p] = fma2(X2[p], pack2(c2, c2), add2(Xp[p], i1));
            B1[p] = fma2(X2[p], pack2(c5, c5), fma2(Xp[p], pack2(c4, c4), ic3));
            B2[p] = fma2(X2[p], pack2(c8, c8), fma2(Xp[p], pack2(c7, c7), ic6));
        }
    }

    u64 T1[8], P[8];
    mm4p_acc(X3b, B2, B1, T1);
    mm4p_acc(X3b, T1, B0, P);

    for (unsigned q = 0; q < sw; ++q) {
        u64 Pb[16];
        bcast(P, Pb);
        u64 C[8];
        mm4p(Pb, P, C);
#pragma unroll
        for (int i = 0; i < 8; ++i) P[i] = C[i];
    }

    ulonglong2* op = reinterpret_cast<ulonglong2*>(out) + (size_t)idx * 4;
    __stcs(op + 0, make_ulonglong2(P[0], P[1]));
    __stcs(op + 1, make_ulonglong2(P[2], P[3]));
    __stcs(op + 2, make_ulonglong2(P[4], P[5]));
    __stcs(op + 3, make_ulonglong2(P[6], P[7]));
}

__device__ __forceinline__ void load_mat(const float* __restrict__ rate,
                                         const float* __restrict__ time,
                                         int idx, u64* __restrict__ Ap, float& t) {
    const ulonglong2* ap = reinterpret_cast<const ulonglong2*>(rate) + (size_t)idx * 4;
    ulonglong2 l0 = __ldcs(ap + 0);
    ulonglong2 l1 = __ldcs(ap + 1);
    ulonglong2 l2 = __ldcs(ap + 2);
    ulonglong2 l3 = __ldcs(ap + 3);
    Ap[0] = l0.x; Ap[1] = l0.y; Ap[2] = l1.x; Ap[3] = l1.y;
    Ap[4] = l2.x; Ap[5] = l2.y; Ap[6] = l3.x; Ap[7] = l3.y;
    t = __ldg(time + (idx >> SEQ_SHIFT));
}

__global__ __launch_bounds__(TPB, 3)
void expm44_kernel(const float* __restrict__ rate,   // [NMAT, 16]
                   const float* __restrict__ time,   // [64]
                   float* __restrict__ out)          // [NMAT, 16]
{
    int idx = blockIdx.x * TPB + threadIdx.x;

    // Prologue load.
    u64 A0[8]; float t0;
    load_mat(rate, time, idx, A0, t0);

    // Grid-stride loop with one-deep register prefetch.
    // Boundary (NMAT % STRIDE = 51200) is a multiple of 32 -> the prefetch
    // predicate and trip count are warp-uniform.
    while (true) {
        const int nxt = idx + STRIDE;
        const bool has_next = (nxt < NMAT);

        u64 A1[8]; float t1 = 0.0f;
        if (has_next) load_mat(rate, time, nxt, A1, t1);   // issue loads early

        expm_one(A0, t0, out, idx);                        // compute + store

        if (!has_next) break;
#pragma unroll
        for (int i = 0; i < 8; ++i) A0[i] = A1[i];
        t0 = t1;
        idx = nxt;
    }
}

extern "C" void kernel_launch(void* const* d_in, const int* in_sizes, int n_in,
                              void* d_out, int out_size) {
    const float* rate = (const float*)d_in[0];
    const float* time = (const float*)d_in[1];
    float* out = (float*)d_out;

    expm44_kernel<<<NBLOCKS, TPB>>>(rate, time, out);
}